// round 11
// baseline (speedup 1.0000x reference)
#include <cuda_runtime.h>

#define N_NODES 50000
#define N_EDGES 800000
#define IN_DIM 128
#define OUT_DIM 64
#define SCAN_BLOCKS 49        // 49 * 1024 = 50176 >= 50000
#define GEMM_BLOCKS ((N_NODES + 63) / 64)          // 782
#define HIST_BLOCKS ((N_EDGES + 255) / 256)        // 3125
#define EDGE_CAP (N_EDGES + N_NODES + 16)          // padded-to-even headroom

// ---------------- scratch (no allocations allowed) ----------------
__device__ float    g_Wh[N_NODES * OUT_DIM];    // projected features
__device__ float    g_adst[N_NODES];            // Wh . A_w[:64]
__device__ float    g_asrc[N_NODES];            // Wh . A_w[64:]
__device__ int      g_off[N_NODES + 1];         // padded-even CSR offsets (by dst)
__device__ int      g_cursor[N_NODES];          // histogram counts -> fill cursors
__device__ __align__(16) int2 g_edge[EDGE_CAP]; // {src id, weight bits} grouped by dst
__device__ int      g_bsum[SCAN_BLOCKS];        // per-block scan totals
__device__ int      g_flag[SCAN_BLOCKS];        // publish flags for lookback
__device__ unsigned g_maxd, g_maxs;             // global max of adst/asrc (sortable)

__device__ __forceinline__ unsigned f2sort(float f) {
    unsigned b = __float_as_uint(f);
    return (b & 0x80000000u) ? ~b : (b | 0x80000000u);
}
__device__ __forceinline__ float sort2f(unsigned u) {
    return __uint_as_float((u & 0x80000000u) ? (u & 0x7fffffffu) : ~u);
}

// ---- packed f32x2 helpers (FFMA2: 2 fp32 FMAs / instruction, exact) ------
__device__ __forceinline__ unsigned long long pk2(float lo, float hi) {
    unsigned long long r;
    asm("mov.b64 %0, {%1, %2};" : "=l"(r) : "f"(lo), "f"(hi));
    return r;
}
__device__ __forceinline__ void fma2(unsigned long long& d,
                                     unsigned long long a, unsigned long long b) {
    asm("fma.rn.f32x2 %0, %1, %2, %0;" : "+l"(d) : "l"(a), "l"(b));
}
__device__ __forceinline__ void upk2(unsigned long long v, float& lo, float& hi) {
    asm("mov.b64 {%0, %1}, %2;" : "=f"(lo), "=f"(hi) : "l"(v));
}

// ---------------- kernel 0: zero histogram + flags + init maxes -----------
__global__ void k_zero() {
    int i = blockIdx.x * blockDim.x + threadIdx.x;
    if (i < N_NODES) g_cursor[i] = 0;
    if (i < SCAN_BLOCKS) g_flag[i] = 0;
    if (i == 0) { g_maxd = 0x007FFFFFu; g_maxs = 0x007FFFFFu; }
}

// ------- kernel 1: dual-role grid: GEMM blocks + histogram blocks ---------
__global__ __launch_bounds__(256) void k_gemm_hist(
    const float* __restrict__ h, const float* __restrict__ Ww,
    const float* __restrict__ Wb, const float* __restrict__ Aw,
    const int* __restrict__ dst)
{
    if (blockIdx.x >= GEMM_BLOCKS) {
        int e = (blockIdx.x - GEMM_BLOCKS) * 256 + threadIdx.x;
        if (e < N_EDGES) atomicAdd(&g_cursor[dst[e]], 1);
        return;
    }

    __shared__ float sh_h[64][65];
    __shared__ __align__(16) float sW[64][64];

    const int tid = threadIdx.x;
    const int cg  = tid & 7;
    const int r0  = tid >> 3;
    const int row0 = blockIdx.x * 64;

    unsigned long long acc2[2][4];
#pragma unroll
    for (int r = 0; r < 2; r++)
#pragma unroll
        for (int j = 0; j < 4; j++) acc2[r][j] = 0ull;

    for (int kc = 0; kc < IN_DIM; kc += 64) {
        __syncthreads();
#pragma unroll
        for (int p = 0; p < 4; p++) {
            int idx = p * 256 + tid;
            int row = idx >> 4;
            int c4  = idx & 15;
            int gr  = row0 + row;
            float4 v = make_float4(0.f, 0.f, 0.f, 0.f);
            if (gr < N_NODES)
                v = *reinterpret_cast<const float4*>(&h[gr * IN_DIM + kc + c4 * 4]);
            sh_h[row][c4 * 4 + 0] = v.x;
            sh_h[row][c4 * 4 + 1] = v.y;
            sh_h[row][c4 * 4 + 2] = v.z;
            sh_h[row][c4 * 4 + 3] = v.w;
        }
#pragma unroll
        for (int p = 0; p < 4; p++) {
            int idx = p * 256 + tid;
            int k  = idx >> 4;
            int c4 = idx & 15;
            float4 v = *reinterpret_cast<const float4*>(&Ww[(kc + k) * OUT_DIM + c4 * 4]);
            *reinterpret_cast<float4*>(&sW[k][c4 * 4]) = v;
        }
        __syncthreads();

#pragma unroll
        for (int k = 0; k < 64; k++) {
            float a0 = sh_h[r0][k];
            float a1 = sh_h[r0 + 32][k];
            unsigned long long a0p = pk2(a0, a0);
            unsigned long long a1p = pk2(a1, a1);
            // packed pairs straight out of shared: (f[2j], f[2j+1]) == f32x2
            ulonglong2 W0 = *reinterpret_cast<const ulonglong2*>(&sW[k][cg * 8]);
            ulonglong2 W1 = *reinterpret_cast<const ulonglong2*>(&sW[k][cg * 8 + 4]);
            fma2(acc2[0][0], a0p, W0.x);
            fma2(acc2[0][1], a0p, W0.y);
            fma2(acc2[0][2], a0p, W1.x);
            fma2(acc2[0][3], a0p, W1.y);
            fma2(acc2[1][0], a1p, W0.x);
            fma2(acc2[1][1], a1p, W0.y);
            fma2(acc2[1][2], a1p, W1.x);
            fma2(acc2[1][3], a1p, W1.y);
        }
    }

    // unpack to scalars for the epilogue
    float acc[2][8];
#pragma unroll
    for (int r = 0; r < 2; r++)
#pragma unroll
        for (int j = 0; j < 4; j++)
            upk2(acc2[r][j], acc[r][2 * j], acc[r][2 * j + 1]);

#pragma unroll
    for (int j = 0; j < 8; j++) {
        float b = Wb[cg * 8 + j];
        acc[0][j] += b;
        acc[1][j] += b;
    }

    float pd[2] = {0.f, 0.f}, ps[2] = {0.f, 0.f};
#pragma unroll
    for (int j = 0; j < 8; j++) {
        float a1v = Aw[cg * 8 + j];
        float a2v = Aw[OUT_DIM + cg * 8 + j];
        pd[0] += acc[0][j] * a1v; ps[0] += acc[0][j] * a2v;
        pd[1] += acc[1][j] * a1v; ps[1] += acc[1][j] * a2v;
    }
#pragma unroll
    for (int off = 1; off < 8; off <<= 1) {
        pd[0] += __shfl_xor_sync(0xffffffffu, pd[0], off);
        ps[0] += __shfl_xor_sync(0xffffffffu, ps[0], off);
        pd[1] += __shfl_xor_sync(0xffffffffu, pd[1], off);
        ps[1] += __shfl_xor_sync(0xffffffffu, ps[1], off);
    }

#pragma unroll
    for (int r = 0; r < 2; r++) {
        int gr = row0 + r0 + r * 32;
        if (gr < N_NODES) {
            float4 o0 = make_float4(acc[r][0], acc[r][1], acc[r][2], acc[r][3]);
            float4 o1 = make_float4(acc[r][4], acc[r][5], acc[r][6], acc[r][7]);
            *reinterpret_cast<float4*>(&g_Wh[gr * OUT_DIM + cg * 8])     = o0;
            *reinterpret_cast<float4*>(&g_Wh[gr * OUT_DIM + cg * 8 + 4]) = o1;
            if (cg == 0) {
                g_adst[gr] = pd[r];
                g_asrc[gr] = ps[r];
                atomicMax(&g_maxd, f2sort(pd[r]));
                atomicMax(&g_maxs, f2sort(ps[r]));
            }
        }
    }
}

// -------- single-kernel scan over EVEN-PADDED degrees + pad-slot init -----
// 49 blocks, all resident in wave 1 (<< 148 SMs) -> spin lookback is safe.
__global__ __launch_bounds__(1024) void k_scan() {
    __shared__ int wsum[32];
    __shared__ int sbase;
    int b    = blockIdx.x;
    int gid  = b * 1024 + threadIdx.x;
    int lane = threadIdx.x & 31;
    int wid  = threadIdx.x >> 5;

    int deg = (gid < N_NODES) ? g_cursor[gid] : 0;
    int v = deg + (deg & 1);           // pad to even
    int x = v;
#pragma unroll
    for (int o = 1; o < 32; o <<= 1) {
        int t = __shfl_up_sync(0xffffffffu, x, o);
        if (lane >= o) x += t;
    }
    if (lane == 31) wsum[wid] = x;
    __syncthreads();
    if (wid == 0) {
        int y = wsum[lane];
#pragma unroll
        for (int o = 1; o < 32; o <<= 1) {
            int t = __shfl_up_sync(0xffffffffu, y, o);
            if (lane >= o) y += t;
        }
        wsum[lane] = y;
    }
    __syncthreads();
    int wbase = (wid > 0) ? wsum[wid - 1] : 0;
    int local_exc = wbase + x - v;

    if (threadIdx.x == 1023) {
        g_bsum[b] = wbase + x;
        __threadfence();
        atomicExch(&g_flag[b], 1);
    }

    if (wid == 0) {
        int sum = 0;
        for (int i = lane; i < b; i += 32) {
            while (atomicAdd(&g_flag[i], 0) == 0) { }
            sum += g_bsum[i];
        }
#pragma unroll
        for (int o = 16; o; o >>= 1) sum += __shfl_xor_sync(0xffffffffu, sum, o);
        if (lane == 0) sbase = sum;
    }
    __syncthreads();

    if (gid < N_NODES) {
        int o = local_exc + sbase;
        g_off[gid] = o;
        g_cursor[gid] = o;
        if (deg & 1) g_edge[o + deg] = make_int2(0, 0);   // zero the pad slot
    }
    if (b == SCAN_BLOCKS - 1 && threadIdx.x == 1023)
        g_off[N_NODES] = sbase + wbase + x;               // total padded length
}

// ---------------- fill CSR + fused edge-weight computation (ILP 2) --------
__global__ void k_fill(const int* __restrict__ src, const int* __restrict__ dst,
                       const float* __restrict__ Ab) {
    int t = blockIdx.x * blockDim.x + threadIdx.x;
    if (t * 2 >= N_EDGES) return;     // N_EDGES is even
    int2 s2 = __ldg(reinterpret_cast<const int2*>(src) + t);
    int2 d2 = __ldg(reinterpret_cast<const int2*>(dst) + t);

    float ab = Ab[0];
    float xb = sort2f(g_maxd) + sort2f(g_maxs) + ab;   // global stabilizer
    float M  = xb > 0.f ? xb : 0.2f * xb;

    int p0 = atomicAdd(&g_cursor[d2.x], 1);
    int p1 = atomicAdd(&g_cursor[d2.y], 1);

    float x0 = __ldg(&g_adst[d2.x]) + __ldg(&g_asrc[s2.x]) + ab;
    float x1 = __ldg(&g_adst[d2.y]) + __ldg(&g_asrc[s2.y]) + ab;
    x0 = (x0 > 0.f ? x0 : 0.2f * x0) - M;
    x1 = (x1 > 0.f ? x1 : 0.2f * x1) - M;

    g_edge[p0] = make_int2(s2.x, __float_as_int(__expf(x0)));
    g_edge[p1] = make_int2(s2.y, __float_as_int(__expf(x1)));
}

// ---------------- gather: normalize + weighted aggregate ------------------
// One warp per dst node; half-warps process edge pairs (float4/16-lane rows).
__global__ __launch_bounds__(256) void k_gather(float4* __restrict__ out4)
{
    int warp = (blockIdx.x * 256 + threadIdx.x) >> 5;
    int lane = threadIdx.x & 31;
    if (warp >= N_NODES) return;

    int off0 = g_off[warp];
    int off1 = g_off[warp + 1];       // even-length segment

    const float4* __restrict__ Wh4 = reinterpret_cast<const float4*>(g_Wh);
    int half = lane >> 4;             // 0: even edge of pair, 1: odd edge
    int hl   = lane & 15;

    float4 acc = make_float4(0.f, 0.f, 0.f, 0.f);
    float den = 0.f;

    int j = off0;
    for (; j + 4 <= off1; j += 4) {
        int4 p0 = __ldg(reinterpret_cast<const int4*>(&g_edge[j]));      // edges j, j+1
        int4 p1 = __ldg(reinterpret_cast<const int4*>(&g_edge[j + 2]));  // edges j+2, j+3
        int   s0 = half ? p0.z : p0.x;
        float w0 = __int_as_float(half ? p0.w : p0.y);
        int   s1 = half ? p1.z : p1.x;
        float w1 = __int_as_float(half ? p1.w : p1.y);
        float4 v0 = Wh4[s0 * 16 + hl];
        float4 v1 = Wh4[s1 * 16 + hl];
        acc.x += w0 * v0.x; acc.y += w0 * v0.y;
        acc.z += w0 * v0.z; acc.w += w0 * v0.w;
        acc.x += w1 * v1.x; acc.y += w1 * v1.y;
        acc.z += w1 * v1.z; acc.w += w1 * v1.w;
        den += w0 + w1;
    }
    if (j < off1) {                   // exactly one pair left
        int4 p0 = __ldg(reinterpret_cast<const int4*>(&g_edge[j]));
        int   s0 = half ? p0.z : p0.x;
        float w0 = __int_as_float(half ? p0.w : p0.y);
        float4 v0 = Wh4[s0 * 16 + hl];
        acc.x += w0 * v0.x; acc.y += w0 * v0.y;
        acc.z += w0 * v0.z; acc.w += w0 * v0.w;
        den += w0;
    }

    // combine the two half-warps (same node, disjoint edge subsets)
    acc.x += __shfl_xor_sync(0xffffffffu, acc.x, 16);
    acc.y += __shfl_xor_sync(0xffffffffu, acc.y, 16);
    acc.z += __shfl_xor_sync(0xffffffffu, acc.z, 16);
    acc.w += __shfl_xor_sync(0xffffffffu, acc.w, 16);
    den   += __shfl_xor_sync(0xffffffffu, den, 16);

    float inv = (off1 > off0) ? 1.f / den : 0.f;   // isolated node -> zeros
    if (half == 0)
        out4[warp * 16 + hl] = make_float4(acc.x * inv, acc.y * inv,
                                           acc.z * inv, acc.w * inv);
}

// ---------------- launch ----------------
extern "C" void kernel_launch(void* const* d_in, const int* in_sizes, int n_in,
                              void* d_out, int out_size) {
    const float* h   = (const float*)d_in[0];
    const float* Ww  = (const float*)d_in[1];
    const float* Wb  = (const float*)d_in[2];
    const float* Aw  = (const float*)d_in[3];
    const float* Ab  = (const float*)d_in[4];
    const int*   src = (const int*)d_in[5];
    const int*   dst = (const int*)d_in[6];
    float4* out4 = (float4*)d_out;

    k_zero<<<(N_NODES + 255) / 256, 256>>>();
    k_gemm_hist<<<GEMM_BLOCKS + HIST_BLOCKS, 256>>>(h, Ww, Wb, Aw, dst);
    k_scan<<<SCAN_BLOCKS, 1024>>>();
    k_fill<<<(N_EDGES / 2 + 255) / 256, 256>>>(src, dst, Ab);
    k_gather<<<(N_NODES * 32 + 255) / 256, 256>>>(out4);
}

// round 12
// speedup vs baseline: 1.0392x; 1.0392x over previous
#include <cuda_runtime.h>

#define N_NODES 50000
#define N_EDGES 800000
#define IN_DIM 128
#define OUT_DIM 64

#define GEMM_BLOCKS 782        // ceil(N_NODES/64)
#define HIST_BLOCKS 1563       // ceil(N_EDGES/2/256)
#define SCAN_BLOCKS 49         // 49*256*4 = 50176 >= N_NODES
#define FILL_BLOCKS 1563       // ceil(N_EDGES/2/256)
#define MEGA_BLOCKS (GEMM_BLOCKS + HIST_BLOCKS + SCAN_BLOCKS + FILL_BLOCKS)

// ---------------- scratch (no allocations allowed) ----------------
__device__ float    g_Wh[N_NODES * OUT_DIM];   // projected features
__device__ float    g_adst[N_NODES];           // Wh . A_w[:64]
__device__ float    g_asrc[N_NODES];           // Wh . A_w[64:]
__device__ int      g_off[N_NODES + 1];        // CSR offsets (by dst)
__device__ int      g_cursor[N_NODES];         // hist counts -> fill cursors (0 at launch entry)
__device__ int2     g_edge[N_EDGES];           // {src id, weight bits} grouped by dst
__device__ int      g_bsum[SCAN_BLOCKS];       // per-scan-block totals
__device__ int      g_flag[SCAN_BLOCKS];       // scan publish flags (0 at launch entry)
__device__ int      g_cnt_gemm, g_cnt_hist, g_cnt_scan;   // phase counters (0 at entry)
__device__ unsigned g_maxd = 0x007FFFFFu;      // global max of adst (sortable bits)
__device__ unsigned g_maxs = 0x007FFFFFu;      // global max of asrc (sortable bits)

__device__ __forceinline__ unsigned f2sort(float f) {
    unsigned b = __float_as_uint(f);
    return (b & 0x80000000u) ? ~b : (b | 0x80000000u);
}
__device__ __forceinline__ float sort2f(unsigned u) {
    return __uint_as_float((u & 0x80000000u) ? (u & 0x7fffffffu) : ~u);
}

// =================== MEGA KERNEL: gemm | hist | scan | fill ===============
// Roles by blockIdx.x, in dispatch order. A role only spins on counters
// advanced by LOWER-bid blocks (decoupled-lookback forward-progress model).
__global__ __launch_bounds__(256) void k_mega(
    const float* __restrict__ h, const float* __restrict__ Ww,
    const float* __restrict__ Wb, const float* __restrict__ Aw,
    const float* __restrict__ Ab,
    const int* __restrict__ src, const int* __restrict__ dst)
{
    // one shared pool, aliased per role (gemm is the largest user: 33024 B)
    __shared__ __align__(16) float smem_pool[64 * 65 + 64 * 64];

    const int tid = threadIdx.x;
    int b = blockIdx.x;

    // ---------------------------- GEMM role -------------------------------
    if (b < GEMM_BLOCKS) {
#define SH_H(r, c) smem_pool[(r) * 65 + (c)]
#define SW(k, c)   smem_pool[64 * 65 + (k) * 64 + (c)]
        const int cg  = tid & 7;
        const int r0  = tid >> 3;
        const int lane = tid & 31;
        const int wid  = tid >> 5;
        const int row0 = b * 64;

        float acc[2][8];
#pragma unroll
        for (int r = 0; r < 2; r++)
#pragma unroll
            for (int j = 0; j < 8; j++) acc[r][j] = 0.f;

        for (int kc = 0; kc < IN_DIM; kc += 64) {
            __syncthreads();
#pragma unroll
            for (int p = 0; p < 4; p++) {
                int idx = p * 256 + tid;
                int row = idx >> 4;
                int c4  = idx & 15;
                int gr  = row0 + row;
                float4 v = make_float4(0.f, 0.f, 0.f, 0.f);
                if (gr < N_NODES)
                    v = *reinterpret_cast<const float4*>(&h[gr * IN_DIM + kc + c4 * 4]);
                SH_H(row, c4 * 4 + 0) = v.x;
                SH_H(row, c4 * 4 + 1) = v.y;
                SH_H(row, c4 * 4 + 2) = v.z;
                SH_H(row, c4 * 4 + 3) = v.w;
            }
#pragma unroll
            for (int p = 0; p < 4; p++) {
                int idx = p * 256 + tid;
                int k  = idx >> 4;
                int c4 = idx & 15;
                float4 v = *reinterpret_cast<const float4*>(&Ww[(kc + k) * OUT_DIM + c4 * 4]);
                *reinterpret_cast<float4*>(&SW(k, c4 * 4)) = v;
            }
            __syncthreads();

#pragma unroll
            for (int k = 0; k < 64; k++) {
                float a0 = SH_H(r0, k);
                float a1 = SH_H(r0 + 32, k);
                float4 w0 = *reinterpret_cast<const float4*>(&SW(k, cg * 8));
                float4 w1 = *reinterpret_cast<const float4*>(&SW(k, cg * 8 + 4));
                acc[0][0] += a0 * w0.x; acc[0][1] += a0 * w0.y;
                acc[0][2] += a0 * w0.z; acc[0][3] += a0 * w0.w;
                acc[0][4] += a0 * w1.x; acc[0][5] += a0 * w1.y;
                acc[0][6] += a0 * w1.z; acc[0][7] += a0 * w1.w;
                acc[1][0] += a1 * w0.x; acc[1][1] += a1 * w0.y;
                acc[1][2] += a1 * w0.z; acc[1][3] += a1 * w0.w;
                acc[1][4] += a1 * w1.x; acc[1][5] += a1 * w1.y;
                acc[1][6] += a1 * w1.z; acc[1][7] += a1 * w1.w;
            }
        }

#pragma unroll
        for (int j = 0; j < 8; j++) {
            float bb = Wb[cg * 8 + j];
            acc[0][j] += bb;
            acc[1][j] += bb;
        }

        float pd[2] = {0.f, 0.f}, ps[2] = {0.f, 0.f};
#pragma unroll
        for (int j = 0; j < 8; j++) {
            float a1v = Aw[cg * 8 + j];
            float a2v = Aw[OUT_DIM + cg * 8 + j];
            pd[0] += acc[0][j] * a1v; ps[0] += acc[0][j] * a2v;
            pd[1] += acc[1][j] * a1v; ps[1] += acc[1][j] * a2v;
        }
#pragma unroll
        for (int off = 1; off < 8; off <<= 1) {
            pd[0] += __shfl_xor_sync(0xffffffffu, pd[0], off);
            ps[0] += __shfl_xor_sync(0xffffffffu, ps[0], off);
            pd[1] += __shfl_xor_sync(0xffffffffu, pd[1], off);
            ps[1] += __shfl_xor_sync(0xffffffffu, ps[1], off);
        }

        float md = -3.4e38f, ms = -3.4e38f;
#pragma unroll
        for (int r = 0; r < 2; r++) {
            int gr = row0 + r0 + r * 32;
            if (gr < N_NODES) {
                float4 o0 = make_float4(acc[r][0], acc[r][1], acc[r][2], acc[r][3]);
                float4 o1 = make_float4(acc[r][4], acc[r][5], acc[r][6], acc[r][7]);
                *reinterpret_cast<float4*>(&g_Wh[gr * OUT_DIM + cg * 8])     = o0;
                *reinterpret_cast<float4*>(&g_Wh[gr * OUT_DIM + cg * 8 + 4]) = o1;
                if (cg == 0) {
                    g_adst[gr] = pd[r];
                    g_asrc[gr] = ps[r];
                }
                md = fmaxf(md, pd[r]);
                ms = fmaxf(ms, ps[r]);
            }
        }
        // block-level max reduce -> 2 atomics per block
#pragma unroll
        for (int o = 16; o; o >>= 1) {
            md = fmaxf(md, __shfl_xor_sync(0xffffffffu, md, o));
            ms = fmaxf(ms, __shfl_xor_sync(0xffffffffu, ms, o));
        }
        __syncthreads();                       // smem pool reuse safe
        if (lane == 0) { smem_pool[wid] = md; smem_pool[8 + wid] = ms; }
        __syncthreads();
        if (tid == 0) {
            float a = smem_pool[0], s = smem_pool[8];
#pragma unroll
            for (int w = 1; w < 8; w++) {
                a = fmaxf(a, smem_pool[w]);
                s = fmaxf(s, smem_pool[8 + w]);
            }
            atomicMax(&g_maxd, f2sort(a));
            atomicMax(&g_maxs, f2sort(s));
            __threadfence();
            atomicAdd(&g_cnt_gemm, 1);
        }
        return;
#undef SH_H
#undef SW
    }
    b -= GEMM_BLOCKS;

    // ---------------------------- HIST role -------------------------------
    if (b < HIST_BLOCKS) {
        int t = b * 256 + tid;
        if (t * 2 < N_EDGES) {
            int2 d2 = __ldg(reinterpret_cast<const int2*>(dst) + t);
            atomicAdd(&g_cursor[d2.x], 1);
            atomicAdd(&g_cursor[d2.y], 1);
        }
        __syncthreads();
        if (tid == 0) { __threadfence(); atomicAdd(&g_cnt_hist, 1); }
        return;
    }
    b -= HIST_BLOCKS;

    // ---------------------------- SCAN role -------------------------------
    if (b < SCAN_BLOCKS) {
        int* ipool = reinterpret_cast<int*>(smem_pool);  // [0..7] warp tot, [8] total, [9] sbase
        const int lane = tid & 31;
        const int wid  = tid >> 5;

        if (tid == 0)
            while (atomicAdd(&g_cnt_hist, 0) < HIST_BLOCKS) __nanosleep(128);
        __syncthreads();
        __threadfence();

        int n0 = b * 1024 + tid * 4;
        int deg[4]; int tsum = 0;
#pragma unroll
        for (int i = 0; i < 4; i++) {
            int n = n0 + i;
            deg[i] = (n < N_NODES) ? g_cursor[n] : 0;
            tsum += deg[i];
        }
        // warp inclusive scan of tsum
        int x = tsum;
#pragma unroll
        for (int o = 1; o < 32; o <<= 1) {
            int t2 = __shfl_up_sync(0xffffffffu, x, o);
            if (lane >= o) x += t2;
        }
        if (lane == 31) ipool[wid] = x;
        __syncthreads();
        if (tid == 0) {
            int run = 0;
#pragma unroll
            for (int w = 0; w < 8; w++) { int v = ipool[w]; ipool[w] = run; run += v; }
            ipool[8] = run;                 // block total
            g_bsum[b] = run;
            __threadfence();
            atomicExch(&g_flag[b], 1);
        }
        __syncthreads();
        int exc = ipool[wid] + x - tsum;    // block-local exclusive prefix

        if (wid == 0) {                     // lookback over lower-bid scan blocks
            int sum = 0;
            for (int i = lane; i < b; i += 32) {
                while (atomicAdd(&g_flag[i], 0) == 0) __nanosleep(64);
                sum += atomicAdd(&g_bsum[i], 0);
            }
#pragma unroll
            for (int o = 16; o; o >>= 1) sum += __shfl_xor_sync(0xffffffffu, sum, o);
            if (lane == 0) ipool[9] = sum;
        }
        __syncthreads();

        int run = ipool[9] + exc;
#pragma unroll
        for (int i = 0; i < 4; i++) {
            int n = n0 + i;
            if (n < N_NODES) {
                g_off[n] = run;
                g_cursor[n] = run;
                run += deg[i];
            }
        }
        if (b == SCAN_BLOCKS - 1 && tid == 255) g_off[N_NODES] = N_EDGES;
        __syncthreads();
        if (tid == 0) { __threadfence(); atomicAdd(&g_cnt_scan, 1); }
        return;
    }
    b -= SCAN_BLOCKS;

    // ---------------------------- FILL role -------------------------------
    {
        if (tid == 0) {
            while (atomicAdd(&g_cnt_scan, 0) < SCAN_BLOCKS) __nanosleep(128);
            while (atomicAdd(&g_cnt_gemm, 0) < GEMM_BLOCKS) __nanosleep(128);
        }
        __syncthreads();
        __threadfence();

        int t = b * 256 + tid;
        if (t * 2 >= N_EDGES) return;
        int2 s2 = __ldg(reinterpret_cast<const int2*>(src) + t);
        int2 d2 = __ldg(reinterpret_cast<const int2*>(dst) + t);

        float ab = Ab[0];
        float xb = sort2f(g_maxd) + sort2f(g_maxs) + ab;   // global stabilizer
        float M  = xb > 0.f ? xb : 0.2f * xb;

        int p0 = atomicAdd(&g_cursor[d2.x], 1);
        int p1 = atomicAdd(&g_cursor[d2.y], 1);

        float x0 = __ldg(&g_adst[d2.x]) + __ldg(&g_asrc[s2.x]) + ab;
        float x1 = __ldg(&g_adst[d2.y]) + __ldg(&g_asrc[s2.y]) + ab;
        x0 = (x0 > 0.f ? x0 : 0.2f * x0) - M;
        x1 = (x1 > 0.f ? x1 : 0.2f * x1) - M;

        g_edge[p0] = make_int2(s2.x, __float_as_int(__expf(x0)));
        g_edge[p1] = make_int2(s2.y, __float_as_int(__expf(x1)));
    }
}

// =================== GATHER: normalize + aggregate + state reset ==========
// One warp per dst node (round-9 proven body). Also restores all scratch
// state (cursor/flags/counters/maxes) so every launch starts identically.
__global__ __launch_bounds__(256) void k_gather(float2* __restrict__ out2)
{
    int gtid = blockIdx.x * 256 + threadIdx.x;

    // ---- state reset for next launch (no reader of these in this kernel) --
    if (gtid < SCAN_BLOCKS) g_flag[gtid] = 0;
    if (gtid == SCAN_BLOCKS)     { g_cnt_gemm = 0; g_cnt_hist = 0; g_cnt_scan = 0; }
    if (gtid == SCAN_BLOCKS + 1) { g_maxd = 0x007FFFFFu; g_maxs = 0x007FFFFFu; }

    int warp = gtid >> 5;
    int lane = threadIdx.x & 31;
    if (warp >= N_NODES) return;
    if (lane == 0) g_cursor[warp] = 0;       // reset fill cursor

    int off0 = g_off[warp];
    int off1 = g_off[warp + 1];

    const float2* __restrict__ Wh2 = reinterpret_cast<const float2*>(g_Wh);
    float2 acc = make_float2(0.f, 0.f);
    float den = 0.f;

    int j = off0;
    for (; j + 4 <= off1; j += 4) {
        int2 e0 = __ldg(&g_edge[j]);
        int2 e1 = __ldg(&g_edge[j + 1]);
        int2 e2 = __ldg(&g_edge[j + 2]);
        int2 e3 = __ldg(&g_edge[j + 3]);
        float w0 = __int_as_float(e0.y);
        float w1 = __int_as_float(e1.y);
        float w2 = __int_as_float(e2.y);
        float w3 = __int_as_float(e3.y);
        float2 v0 = Wh2[e0.x * 32 + lane];
        float2 v1 = Wh2[e1.x * 32 + lane];
        float2 v2 = Wh2[e2.x * 32 + lane];
        float2 v3 = Wh2[e3.x * 32 + lane];
        acc.x += w0 * v0.x; acc.y += w0 * v0.y;
        acc.x += w1 * v1.x; acc.y += w1 * v1.y;
        acc.x += w2 * v2.x; acc.y += w2 * v2.y;
        acc.x += w3 * v3.x; acc.y += w3 * v3.y;
        den += (w0 + w1) + (w2 + w3);
    }
    for (; j < off1; j++) {
        int2 e0 = __ldg(&g_edge[j]);
        float w = __int_as_float(e0.y);
        float2 v = Wh2[e0.x * 32 + lane];
        acc.x += w * v.x;
        acc.y += w * v.y;
        den += w;
    }

    float inv = (off1 > off0) ? 1.f / den : 0.f;   // isolated node -> zeros
    out2[warp * 32 + lane] = make_float2(acc.x * inv, acc.y * inv);
}

// ---------------- launch ----------------
extern "C" void kernel_launch(void* const* d_in, const int* in_sizes, int n_in,
                              void* d_out, int out_size) {
    const float* h   = (const float*)d_in[0];
    const float* Ww  = (const float*)d_in[1];
    const float* Wb  = (const float*)d_in[2];
    const float* Aw  = (const float*)d_in[3];
    const float* Ab  = (const float*)d_in[4];
    const int*   src = (const int*)d_in[5];
    const int*   dst = (const int*)d_in[6];
    float2* out2 = (float2*)d_out;

    k_mega<<<MEGA_BLOCKS, 256>>>(h, Ww, Wb, Aw, Ab, src, dst);
    k_gather<<<(N_NODES * 32 + 255) / 256, 256>>>(out2);
}